// round 16
// baseline (speedup 1.0000x reference)
#include <cuda_runtime.h>
#include <cuda_bf16.h>
#include <math.h>
#include <stdint.h>

#define BATCH   32768
#define ROWS    64
#define NBLK    (BATCH / ROWS)      // 512 gemm blocks
#define CVTBLK  128                 // ctx-convert blocks
#define GRID    (NBLK + CVTBLK)     // 640
#define EMBED   300
#define VOCAB   100000
#define CTXP    304                 // padded bf16 row (608 B)
#define KNEG    10
#define KPAD    320
#define THREADS 256
#define ROWB    656
#define BCHUNK  32
#define NSTEP   20
#define DOTBLK  1024                // dot grid: 32 rows/block, 128 threads

// ---- smem float-index layout (hetero) ----
#define SMF_NLL   0
#define SMF_WCLS  96
#define SMF_BENC  736
#define SMF_BDEC  1056
#define SMF_LGP   1376
#define SMF_LGQ   1504
// ---- smem byte layout (hetero) ----
#define SMB_A     6656
#define SMB_A2    (SMB_A  + ROWS * ROWB)
#define SMB_B     (SMB_A2 + ROWS * ROWB)
#define SM_TOTAL  (SMB_B  + BCHUNK * ROWB)    // 111616 -> 2 blocks/SM

__device__ __nv_bfloat16 g_Wenc[KPAD * KPAD];
__device__ __nv_bfloat16 g_Wdec[KPAD * KPAD];
__device__ __nv_bfloat16 g_ctx[(size_t)VOCAB * CTXP];
__device__ __nv_bfloat16 g_cv[(size_t)BATCH * CTXP];
__device__ float g_nll[NBLK];
__device__ float g_deno[DOTBLK];
__device__ int   g_ctr = 0;

__device__ __forceinline__ uint32_t smem_u32(const void* p) {
    uint32_t a;
    asm("{ .reg .u64 t; cvta.to.shared.u64 t, %1; cvt.u32.u64 %0, t; }" : "=r"(a) : "l"(p));
    return a;
}

__device__ __forceinline__ void ldsm_x4(uint32_t* r, uint32_t addr) {
    asm volatile("ldmatrix.sync.aligned.m8n8.x4.shared.b16 {%0,%1,%2,%3}, [%4];"
                 : "=r"(r[0]), "=r"(r[1]), "=r"(r[2]), "=r"(r[3]) : "r"(addr));
}

__device__ __forceinline__ void mma_bf16(float* d, const uint32_t* a, const uint32_t* b) {
    asm volatile("mma.sync.aligned.m16n8k16.row.col.f32.bf16.bf16.f32 "
                 "{%0,%1,%2,%3},{%4,%5,%6,%7},{%8,%9},{%0,%1,%2,%3};"
                 : "+f"(d[0]), "+f"(d[1]), "+f"(d[2]), "+f"(d[3])
                 : "r"(a[0]), "r"(a[1]), "r"(a[2]), "r"(a[3]), "r"(b[0]), "r"(b[1]));
}

__device__ __forceinline__ uint32_t bf2_bits(float lo, float hi) {
    __nv_bfloat162 t = __floats2bfloat162_rn(lo, hi);
    return *(uint32_t*)&t;
}

#define BFMA2(acc, a, b) \
    asm("fma.rn.bf16x2 %0, %1, %2, %0;" : "+r"(acc) : "r"(a), "r"(b))

// ---------------------------------------------------------------------------
__global__ __launch_bounds__(256) void convert_w(__nv_bfloat16* __restrict__ dst,
                                                 const float* __restrict__ src)
{
    const int idx = blockIdx.x * 256 + threadIdx.x;
    if (idx >= KPAD * KPAD) return;
    const int h = idx / KPAD;
    const int k = idx - h * KPAD;
    dst[idx] = __float2bfloat16((h < 300 && k < 300) ? src[h * 300 + k] : 0.f);
}

// ---------------------------------------------------------------------------
// Heterogeneous kernel: [0,128) convert ctx; [128,640) gemm pipeline.
// A fragments for ks 0..9 are register-resident per GEMM (one ldsm pass).
// ---------------------------------------------------------------------------
__global__ __launch_bounds__(THREADS, 2) void hetero_kernel(
    const int* __restrict__ cen_ids,  const int* __restrict__ labels,
    const float* __restrict__ cen_emb, const float* __restrict__ ctx_emb,
    const float* __restrict__ b_enc,  const float* __restrict__ b_dec,
    const float* __restrict__ W_cls,  const float* __restrict__ b_cls)
{
    const int tid = threadIdx.x;

    if (blockIdx.x < CVTBLK) {
        const int total = VOCAB * 38;
        for (int i = blockIdx.x * THREADS + tid; i < total; i += CVTBLK * THREADS) {
            const int r  = i / 38;
            const int c0 = (i - r * 38) * 8;
            const float* sp = ctx_emb + (size_t)r * EMBED + c0;
            float4 v0 = make_float4(0.f, 0.f, 0.f, 0.f);
            float4 v1 = make_float4(0.f, 0.f, 0.f, 0.f);
            if (c0 < 296) { v0 = *(const float4*)sp; v1 = *(const float4*)(sp + 4); }
            else if (c0 == 296) { v0 = *(const float4*)sp; }
            uint4 o;
            o.x = bf2_bits(v0.x, v0.y);
            o.y = bf2_bits(v0.z, v0.w);
            o.z = bf2_bits(v1.x, v1.y);
            o.w = bf2_bits(v1.z, v1.w);
            *(uint4*)(g_ctx + (size_t)r * CTXP + c0) = o;
        }
        return;
    }

    extern __shared__ char smc[];
    float* smf = (float*)smc;
    const uint32_t sb = smem_u32(smc);
    const int gb   = blockIdx.x - CVTBLK;
    const int wid  = tid >> 5;
    const int lane = tid & 31;
    const int r0   = gb * ROWS;

    for (int i = tid; i < 640; i += THREADS) {
        const int cls = i / KPAD, col = i - cls * KPAD;
        smf[SMF_WCLS + i] = (col < 300) ? W_cls[cls * 300 + col] : 0.f;
    }
    for (int i = tid; i < KPAD; i += THREADS) {
        smf[SMF_BENC + i] = (i < 300) ? b_enc[i] : 0.f;
        smf[SMF_BDEC + i] = (i < 300) ? b_dec[i] : 0.f;
    }
    for (int idx = tid; idx < ROWS * (KPAD / 2); idx += THREADS) {
        const int r = idx / (KPAD / 2);
        const int c = (idx - r * (KPAD / 2)) * 2;
        float2 v = make_float2(0.f, 0.f);
        if (c < 300)
            v = *(const float2*)(cen_emb + (size_t)cen_ids[r0 + r] * EMBED + c);
        *(uint32_t*)(smc + SMB_A + r * ROWB + c * 2) = bf2_bits(v.x, v.y);
    }

    const int mg    = wid & 3;
    const int nhalf = wid >> 2;
    const int m0    = mg * 16;
    const int rowA  = m0 + (lane >> 2);
    const int cq    = (lane & 3) * 2;
    float lg00 = 0.f, lg01 = 0.f, lg10 = 0.f, lg11 = 0.f;

    const uint32_t aAddrG0 = sb + SMB_A  + (uint32_t)(m0 + (lane & 15)) * ROWB
                           + (uint32_t)((lane >> 4) * 8) * 2;
    const uint32_t aAddrG1 = sb + SMB_A2 + (uint32_t)(m0 + (lane & 15)) * ROWB
                           + (uint32_t)((lane >> 4) * 8) * 2;
    const uint32_t bAddr0  = sb + SMB_B
                           + (uint32_t)(nhalf * 16 + ((lane >> 4) << 3) + (lane & 7)) * ROWB
                           + (uint32_t)(((lane >> 3) & 1) * 8) * 2;

    uint4 pre[5];
    {
        const uint4* src = (const uint4*)g_Wenc;
        #pragma unroll
        for (int k = 0; k < 5; ++k) pre[k] = src[tid + k * 256];
    }

    uint32_t areg[10][4];               // A fragments for ks 0..9 (resident per GEMM)

    #pragma unroll 1
    for (int step = 0; step < NSTEP; ++step) {
        const int g  = step / 10;
        const int n0 = (step - g * 10) * BCHUNK;

        __syncthreads();
        #pragma unroll
        for (int k = 0; k < 5; ++k) {
            const int i = tid + k * 256;
            const int r = i / 40, q = i - r * 40;
            *(uint4*)(smc + SMB_B + r * ROWB + q * 16) = pre[k];
        }
        __syncthreads();

        const uint32_t aAddr0 = g ? aAddrG1 : aAddrG0;

        // Load resident A fragments once per GEMM (A/A2 complete + stable here)
        if (step == 0 || step == 10) {
            #pragma unroll
            for (int ks = 0; ks < 10; ++ks)
                ldsm_x4(areg[ks], aAddr0 + ks * 32);
        }

        if (step + 1 < NSTEP) {
            const int s2 = step + 1, g2 = s2 / 10, c2 = s2 - g2 * 10;
            const uint4* src = (const uint4*)(g2 ? g_Wdec : g_Wenc) + c2 * (BCHUNK * 40);
            #pragma unroll
            for (int k = 0; k < 5; ++k) pre[k] = src[tid + k * 256];
        }

        float acc[2][4];
        #pragma unroll
        for (int j = 0; j < 2; ++j)
            #pragma unroll
            for (int i = 0; i < 4; ++i) acc[j][i] = 0.f;

        #pragma unroll 5
        for (int ks = 0; ks < 10; ++ks) {          // resident-A half
            uint32_t b[4];
            ldsm_x4(b, bAddr0 + ks * 32);
            mma_bf16(acc[0], areg[ks], b);
            mma_bf16(acc[1], areg[ks], b + 2);
        }
        #pragma unroll 5
        for (int ks = 10; ks < 20; ++ks) {         // streamed-A half
            uint32_t a[4], b[4];
            ldsm_x4(a, aAddr0 + ks * 32);
            ldsm_x4(b, bAddr0 + ks * 32);
            mma_bf16(acc[0], a, b);
            mma_bf16(acc[1], a, b + 2);
        }

        if (g == 0) {
            #pragma unroll
            for (int j = 0; j < 2; ++j) {
                const int c0 = n0 + nhalf * 16 + j * 8 + cq;
                const float be0 = smf[SMF_BENC + c0], be1 = smf[SMF_BENC + c0 + 1];
                const float v0 = acc[j][0] + be0, v1 = acc[j][1] + be1;
                const float v2 = acc[j][2] + be0, v3 = acc[j][3] + be1;
                const float w00 = smf[SMF_WCLS + c0],       w01 = smf[SMF_WCLS + c0 + 1];
                const float w10 = smf[SMF_WCLS + 320 + c0], w11 = smf[SMF_WCLS + 320 + c0 + 1];
                lg00 += v0 * w00 + v1 * w01;  lg01 += v0 * w10 + v1 * w11;
                lg10 += v2 * w00 + v3 * w01;  lg11 += v2 * w10 + v3 * w11;
                *(uint32_t*)(smc + SMB_A2 + rowA * ROWB + c0 * 2)       = bf2_bits(v0, v1);
                *(uint32_t*)(smc + SMB_A2 + (rowA + 8) * ROWB + c0 * 2) = bf2_bits(v2, v3);
            }
        } else {
            #pragma unroll
            for (int j = 0; j < 2; ++j) {
                const int c0 = n0 + nhalf * 16 + j * 8 + cq;
                if (c0 < CTXP) {
                    const float bd0 = smf[SMF_BDEC + c0], bd1 = smf[SMF_BDEC + c0 + 1];
                    *(uint32_t*)(g_cv + (size_t)(r0 + rowA) * CTXP + c0) =
                        bf2_bits(acc[j][0] + bd0, acc[j][1] + bd1);
                    *(uint32_t*)(g_cv + (size_t)(r0 + rowA + 8) * CTXP + c0) =
                        bf2_bits(acc[j][2] + bd0, acc[j][3] + bd1);
                }
            }
        }
    }

    lg00 += __shfl_xor_sync(0xffffffffu, lg00, 1);
    lg00 += __shfl_xor_sync(0xffffffffu, lg00, 2);
    lg01 += __shfl_xor_sync(0xffffffffu, lg01, 1);
    lg01 += __shfl_xor_sync(0xffffffffu, lg01, 2);
    lg10 += __shfl_xor_sync(0xffffffffu, lg10, 1);
    lg10 += __shfl_xor_sync(0xffffffffu, lg10, 2);
    lg11 += __shfl_xor_sync(0xffffffffu, lg11, 1);
    lg11 += __shfl_xor_sync(0xffffffffu, lg11, 2);
    if ((lane & 3) == 0) {
        const int base = nhalf ? SMF_LGQ : SMF_LGP;
        smf[base + rowA * 2]           = lg00;
        smf[base + rowA * 2 + 1]       = lg01;
        smf[base + (rowA + 8) * 2]     = lg10;
        smf[base + (rowA + 8) * 2 + 1] = lg11;
    }
    __syncthreads();
    if (tid < ROWS) {
        const float l0 = smf[SMF_LGP + tid * 2]     + smf[SMF_LGQ + tid * 2]     + b_cls[0];
        const float l1 = smf[SMF_LGP + tid * 2 + 1] + smf[SMF_LGQ + tid * 2 + 1] + b_cls[1];
        const float m  = fmaxf(l0, l1);
        const float lse = m + log1pf(__expf(fminf(l0, l1) - m));
        smf[SMF_NLL + tid] = lse - (labels[r0 + tid] ? l1 : l0);
    }
    __syncthreads();
    if (tid == 0) {
        float sn = 0.f;
        #pragma unroll
        for (int i = 0; i < ROWS; ++i) sn += smf[SMF_NLL + i];
        g_nll[gb] = sn;
    }
}

// ---------------------------------------------------------------------------
// Dot kernel: 1024 blocks x 128 threads, 2 rows processed per iteration
// (doubled ILP: two independent load/FMA/reduce streams per warp).
// ---------------------------------------------------------------------------
__global__ __launch_bounds__(128) void dot_kernel(const int* __restrict__ ctx_ids,
                                                  const int* __restrict__ neg_ids,
                                                  float* __restrict__ out)
{
    __shared__ float sden[16];
    __shared__ int isLast;
    const int tid  = threadIdx.x;
    const int wid  = tid >> 5;
    const int lane = tid & 31;
    const int o    = lane >> 3;
    const int l    = lane & 7;
    const int r0   = blockIdx.x * 32;

    float accDeno = 0.f;

    #pragma unroll 1
    for (int t = 0; t < 4; ++t) {
        const int gr0 = r0 + wid * 8 + t * 2;
        const int gr1 = gr0 + 1;
        const uint4* cvp0 = (const uint4*)(g_cv + (size_t)gr0 * CTXP);
        const uint4* cvp1 = (const uint4*)(g_cv + (size_t)gr1 * CTXP);

        uint4 cv0[5], cv1[5];
        #pragma unroll
        for (int s = 0; s < 5; ++s) {
            const int e = s * 8 + l;
            cv0[s] = (e < 38) ? cvp0[e] : make_uint4(0u, 0u, 0u, 0u);
            cv1[s] = (e < 38) ? cvp1[e] : make_uint4(0u, 0u, 0u, 0u);
        }

        #pragma unroll
        for (int round = 0; round < 3; ++round) {
            const int j = round * 4 + o;
            const bool valid = (j < 11);
            int w0 = 0, w1 = 0;
            if (valid) {
                w0 = (j == 0) ? ctx_ids[gr0] : neg_ids[gr0 * KNEG + (j - 1)];
                w1 = (j == 0) ? ctx_ids[gr1] : neg_ids[gr1 * KNEG + (j - 1)];
            }
            const uint4* xp0 = (const uint4*)(g_ctx + (size_t)w0 * CTXP);
            const uint4* xp1 = (const uint4*)(g_ctx + (size_t)w1 * CTXP);

            uint32_t a00 = 0u, a01 = 0u, a10 = 0u, a11 = 0u;
            #pragma unroll
            for (int s = 0; s < 5; ++s) {
                const int e = s * 8 + l;
                if (e < 38) {
                    const uint4 x0 = xp0[e];
                    const uint4 x1 = xp1[e];
                    BFMA2(a00, cv0[s].x, x0.x);
                    BFMA2(a01, cv0[s].y, x0.y);
                    BFMA2(a10, cv1[s].x, x1.x);
                    BFMA2(a11, cv1[s].y, x1.y);
                    BFMA2(a00, cv0[s].z, x0.z);
                    BFMA2(a01, cv0[s].w, x0.w);
                    BFMA2(a10, cv1[s].z, x1.z);
                    BFMA2(a11, cv1[s].w, x1.w);
                }
            }
            const float2 f00 = __bfloat1622float2(*(const __nv_bfloat162*)&a00);
            const float2 f01 = __bfloat1622float2(*(const __nv_bfloat162*)&a01);
            const float2 f10 = __bfloat1622float2(*(const __nv_bfloat162*)&a10);
            const float2 f11 = __bfloat1622float2(*(const __nv_bfloat162*)&a11);
            float acc0 = (f00.x + f00.y) + (f01.x + f01.y);
            float acc1 = (f10.x + f10.y) + (f11.x + f11.y);

            acc0 += __shfl_down_sync(0xffffffffu, acc0, 4, 8);
            acc1 += __shfl_down_sync(0xffffffffu, acc1, 4, 8);
            acc0 += __shfl_down_sync(0xffffffffu, acc0, 2, 8);
            acc1 += __shfl_down_sync(0xffffffffu, acc1, 2, 8);
            acc0 += __shfl_down_sync(0xffffffffu, acc0, 1, 8);
            acc1 += __shfl_down_sync(0xffffffffu, acc1, 1, 8);

            if (l == 0 && valid) {
                const float s0 = fminf(fmaxf(acc0, -10.f), 10.f);
                const float s1 = fminf(fmaxf(acc1, -10.f), 10.f);
                if (j == 0) {
                    accDeno += log1pf(__expf(-s0)) + log1pf(__expf(-s1));
                } else {
                    accDeno += log1pf(__expf(s0)) + log1pf(__expf(s1));
                }
            }
        }
    }
    if (l == 0) sden[wid * 4 + o] = accDeno;
    __syncthreads();
    if (tid == 0) {
        float sd = 0.f;
        #pragma unroll
        for (int i = 0; i < 16; ++i) sd += sden[i];
        g_deno[blockIdx.x] = sd;
    }

    // ---- last-block-done finalize (deterministic fixed-order reduce) ----
    __threadfence();
    if (tid == 0) {
        const int c = atomicAdd(&g_ctr, 1);
        isLast = (c == DOTBLK - 1);
    }
    __syncthreads();
    if (!isLast) return;

    __shared__ float rd[128], rn[128];
    float s = 0.f;
    for (int i = tid; i < DOTBLK; i += 128) s += g_deno[i];
    rd[tid] = s;
    float n = 0.f;
    for (int i = tid; i < NBLK; i += 128) n += g_nll[i];
    rn[tid] = n;
    __syncthreads();
    for (int ofs = 64; ofs > 0; ofs >>= 1) {
        if (tid < ofs) { rd[tid] += rd[tid + ofs]; rn[tid] += rn[tid + ofs]; }
        __syncthreads();
    }
    if (tid == 0) {
        const float invB = 1.0f / (float)BATCH;
        float deno = fminf(fmaxf(rd[0] * invB, 1e-5f), 10.f);
        float cono = fminf(fmaxf(rn[0] * invB, 1e-5f), 10.f);
        out[0] = fmaxf(deno + cono, 1e-5f);
        out[1] = deno;
        out[2] = cono;
        g_ctr = 0;                       // reset for next graph replay
    }
}

extern "C" void kernel_launch(void* const* d_in, const int* in_sizes, int n_in,
                              void* d_out, int out_size)
{
    const int*   cen_ids = (const int*)  d_in[0];
    const int*   ctx_ids = (const int*)  d_in[1];
    const int*   neg_ids = (const int*)  d_in[2];
    const int*   labels  = (const int*)  d_in[3];
    const float* cen_emb = (const float*)d_in[4];
    const float* ctx_emb = (const float*)d_in[5];
    const float* W_enc   = (const float*)d_in[6];
    const float* b_enc   = (const float*)d_in[7];
    const float* W_dec   = (const float*)d_in[8];
    const float* b_dec   = (const float*)d_in[9];
    const float* W_cls   = (const float*)d_in[10];
    const float* b_cls   = (const float*)d_in[11];

    __nv_bfloat16* we;  cudaGetSymbolAddress((void**)&we, g_Wenc);
    __nv_bfloat16* wd;  cudaGetSymbolAddress((void**)&wd, g_Wdec);

    const int cBlocks = (KPAD * KPAD + 255) / 256;
    convert_w<<<cBlocks, 256>>>(we, W_enc);
    convert_w<<<cBlocks, 256>>>(wd, W_dec);

    cudaFuncSetAttribute(hetero_kernel,
                         cudaFuncAttributeMaxDynamicSharedMemorySize, SM_TOTAL);
    hetero_kernel<<<GRID, THREADS, SM_TOTAL>>>(
        cen_ids, labels, cen_emb, ctx_emb, b_enc, b_dec, W_cls, b_cls);
    dot_kernel<<<DOTBLK, 128>>>(ctx_ids, neg_ids, (float*)d_out);
}

// round 17
// speedup vs baseline: 1.2258x; 1.2258x over previous
#include <cuda_runtime.h>
#include <cuda_bf16.h>
#include <math.h>
#include <stdint.h>

#define BATCH   32768
#define ROWS    64
#define NBLK    (BATCH / ROWS)      // 512 gemm blocks
#define CVTBLK  128                 // ctx-convert blocks
#define GRID    (NBLK + CVTBLK)     // 640
#define EMBED   300
#define VOCAB   100000
#define CTXP    304                 // padded bf16 row (608 B)
#define KNEG    10
#define KPAD    320
#define THREADS 256
#define ROWB    656
#define BCHUNK  32
#define NSTEP   20
#define DOTBLK  1024                // dot grid: 32 rows/block, 128 threads

// ---- smem float-index layout (hetero) ----
#define SMF_NLL   0
#define SMF_WCLS  96
#define SMF_BENC  736
#define SMF_BDEC  1056
#define SMF_LGP   1376
#define SMF_LGQ   1504
// ---- smem byte layout (hetero) ----
#define SMB_A     6656
#define SMB_A2    (SMB_A  + ROWS * ROWB)
#define SMB_B     (SMB_A2 + ROWS * ROWB)
#define SM_TOTAL  (SMB_B  + BCHUNK * ROWB)    // 111616 -> 2 blocks/SM

__device__ __nv_bfloat16 g_Wenc[KPAD * KPAD];
__device__ __nv_bfloat16 g_Wdec[KPAD * KPAD];
__device__ __nv_bfloat16 g_ctx[(size_t)VOCAB * CTXP];
__device__ __nv_bfloat16 g_cv[(size_t)BATCH * CTXP];
__device__ float g_nll[NBLK];
__device__ float g_deno[DOTBLK];

__device__ __forceinline__ uint32_t smem_u32(const void* p) {
    uint32_t a;
    asm("{ .reg .u64 t; cvta.to.shared.u64 t, %1; cvt.u32.u64 %0, t; }" : "=r"(a) : "l"(p));
    return a;
}

__device__ __forceinline__ void ldsm_x4(uint32_t* r, uint32_t addr) {
    asm volatile("ldmatrix.sync.aligned.m8n8.x4.shared.b16 {%0,%1,%2,%3}, [%4];"
                 : "=r"(r[0]), "=r"(r[1]), "=r"(r[2]), "=r"(r[3]) : "r"(addr));
}

__device__ __forceinline__ void mma_bf16(float* d, const uint32_t* a, const uint32_t* b) {
    asm volatile("mma.sync.aligned.m16n8k16.row.col.f32.bf16.bf16.f32 "
                 "{%0,%1,%2,%3},{%4,%5,%6,%7},{%8,%9},{%0,%1,%2,%3};"
                 : "+f"(d[0]), "+f"(d[1]), "+f"(d[2]), "+f"(d[3])
                 : "r"(a[0]), "r"(a[1]), "r"(a[2]), "r"(a[3]), "r"(b[0]), "r"(b[1]));
}

__device__ __forceinline__ uint32_t bf2_bits(float lo, float hi) {
    __nv_bfloat162 t = __floats2bfloat162_rn(lo, hi);
    return *(uint32_t*)&t;
}

#define BFMA2(acc, a, b) \
    asm("fma.rn.bf16x2 %0, %1, %2, %0;" : "+r"(acc) : "r"(a), "r"(b))

// ---------------------------------------------------------------------------
// Merged weight convert: both W_enc and W_dec in one launch.
// ---------------------------------------------------------------------------
__global__ __launch_bounds__(256) void convert_w2(const float* __restrict__ Wenc,
                                                  const float* __restrict__ Wdec)
{
    const int idx = blockIdx.x * 256 + threadIdx.x;
    const int N = KPAD * KPAD;
    if (idx >= 2 * N) return;
    const int which = idx >= N;
    const int e = which ? (idx - N) : idx;
    const int h = e / KPAD;
    const int k = e - h * KPAD;
    const float* src = which ? Wdec : Wenc;
    const float v = (h < 300 && k < 300) ? src[h * 300 + k] : 0.f;
    (which ? g_Wdec : g_Wenc)[e] = __float2bfloat16(v);
}

// ---------------------------------------------------------------------------
// Heterogeneous kernel: [0,128) convert ctx; [128,640) gemm pipeline.
// ---------------------------------------------------------------------------
__global__ __launch_bounds__(THREADS, 2) void hetero_kernel(
    const int* __restrict__ cen_ids,  const int* __restrict__ labels,
    const float* __restrict__ cen_emb, const float* __restrict__ ctx_emb,
    const float* __restrict__ b_enc,  const float* __restrict__ b_dec,
    const float* __restrict__ W_cls,  const float* __restrict__ b_cls)
{
    const int tid = threadIdx.x;

    if (blockIdx.x < CVTBLK) {
        const int total = VOCAB * 38;
        for (int i = blockIdx.x * THREADS + tid; i < total; i += CVTBLK * THREADS) {
            const int r  = i / 38;
            const int c0 = (i - r * 38) * 8;
            const float* sp = ctx_emb + (size_t)r * EMBED + c0;
            float4 v0 = make_float4(0.f, 0.f, 0.f, 0.f);
            float4 v1 = make_float4(0.f, 0.f, 0.f, 0.f);
            if (c0 < 296) { v0 = *(const float4*)sp; v1 = *(const float4*)(sp + 4); }
            else if (c0 == 296) { v0 = *(const float4*)sp; }
            uint4 o;
            o.x = bf2_bits(v0.x, v0.y);
            o.y = bf2_bits(v0.z, v0.w);
            o.z = bf2_bits(v1.x, v1.y);
            o.w = bf2_bits(v1.z, v1.w);
            *(uint4*)(g_ctx + (size_t)r * CTXP + c0) = o;
        }
        return;
    }

    extern __shared__ char smc[];
    float* smf = (float*)smc;
    const uint32_t sb = smem_u32(smc);
    const int gb   = blockIdx.x - CVTBLK;
    const int wid  = tid >> 5;
    const int lane = tid & 31;
    const int r0   = gb * ROWS;

    for (int i = tid; i < 640; i += THREADS) {
        const int cls = i / KPAD, col = i - cls * KPAD;
        smf[SMF_WCLS + i] = (col < 300) ? W_cls[cls * 300 + col] : 0.f;
    }
    for (int i = tid; i < KPAD; i += THREADS) {
        smf[SMF_BENC + i] = (i < 300) ? b_enc[i] : 0.f;
        smf[SMF_BDEC + i] = (i < 300) ? b_dec[i] : 0.f;
    }
    for (int idx = tid; idx < ROWS * (KPAD / 2); idx += THREADS) {
        const int r = idx / (KPAD / 2);
        const int c = (idx - r * (KPAD / 2)) * 2;
        float2 v = make_float2(0.f, 0.f);
        if (c < 300)
            v = *(const float2*)(cen_emb + (size_t)cen_ids[r0 + r] * EMBED + c);
        *(uint32_t*)(smc + SMB_A + r * ROWB + c * 2) = bf2_bits(v.x, v.y);
    }

    const int mg    = wid & 3;
    const int nhalf = wid >> 2;
    const int m0    = mg * 16;
    const int rowA  = m0 + (lane >> 2);
    const int cq    = (lane & 3) * 2;
    float lg00 = 0.f, lg01 = 0.f, lg10 = 0.f, lg11 = 0.f;

    const uint32_t aAddrG0 = sb + SMB_A  + (uint32_t)(m0 + (lane & 15)) * ROWB
                           + (uint32_t)((lane >> 4) * 8) * 2;
    const uint32_t aAddrG1 = sb + SMB_A2 + (uint32_t)(m0 + (lane & 15)) * ROWB
                           + (uint32_t)((lane >> 4) * 8) * 2;
    const uint32_t bAddr0  = sb + SMB_B
                           + (uint32_t)(nhalf * 16 + ((lane >> 4) << 3) + (lane & 7)) * ROWB
                           + (uint32_t)(((lane >> 3) & 1) * 8) * 2;

    uint4 pre[5];
    {
        const uint4* src = (const uint4*)g_Wenc;
        #pragma unroll
        for (int k = 0; k < 5; ++k) pre[k] = src[tid + k * 256];
    }

    #pragma unroll 1
    for (int step = 0; step < NSTEP; ++step) {
        const int g  = step / 10;
        const int n0 = (step - g * 10) * BCHUNK;

        __syncthreads();
        #pragma unroll
        for (int k = 0; k < 5; ++k) {
            const int i = tid + k * 256;
            const int r = i / 40, q = i - r * 40;
            *(uint4*)(smc + SMB_B + r * ROWB + q * 16) = pre[k];
        }
        __syncthreads();

        if (step + 1 < NSTEP) {
            const int s2 = step + 1, g2 = s2 / 10, c2 = s2 - g2 * 10;
            const uint4* src = (const uint4*)(g2 ? g_Wdec : g_Wenc) + c2 * (BCHUNK * 40);
            #pragma unroll
            for (int k = 0; k < 5; ++k) pre[k] = src[tid + k * 256];
        }

        float acc[2][4];
        #pragma unroll
        for (int j = 0; j < 2; ++j)
            #pragma unroll
            for (int i = 0; i < 4; ++i) acc[j][i] = 0.f;

        const uint32_t aAddr0 = g ? aAddrG1 : aAddrG0;
        #pragma unroll 5
        for (int ks = 0; ks < 20; ++ks) {
            uint32_t a[4], b[4];
            ldsm_x4(a, aAddr0 + ks * 32);
            ldsm_x4(b, bAddr0 + ks * 32);
            mma_bf16(acc[0], a, b);
            mma_bf16(acc[1], a, b + 2);
        }

        if (g == 0) {
            #pragma unroll
            for (int j = 0; j < 2; ++j) {
                const int c0 = n0 + nhalf * 16 + j * 8 + cq;
                const float be0 = smf[SMF_BENC + c0], be1 = smf[SMF_BENC + c0 + 1];
                const float v0 = acc[j][0] + be0, v1 = acc[j][1] + be1;
                const float v2 = acc[j][2] + be0, v3 = acc[j][3] + be1;
                const float w00 = smf[SMF_WCLS + c0],       w01 = smf[SMF_WCLS + c0 + 1];
                const float w10 = smf[SMF_WCLS + 320 + c0], w11 = smf[SMF_WCLS + 320 + c0 + 1];
                lg00 += v0 * w00 + v1 * w01;  lg01 += v0 * w10 + v1 * w11;
                lg10 += v2 * w00 + v3 * w01;  lg11 += v2 * w10 + v3 * w11;
                *(uint32_t*)(smc + SMB_A2 + rowA * ROWB + c0 * 2)       = bf2_bits(v0, v1);
                *(uint32_t*)(smc + SMB_A2 + (rowA + 8) * ROWB + c0 * 2) = bf2_bits(v2, v3);
            }
        } else {
            #pragma unroll
            for (int j = 0; j < 2; ++j) {
                const int c0 = n0 + nhalf * 16 + j * 8 + cq;
                if (c0 < CTXP) {
                    const float bd0 = smf[SMF_BDEC + c0], bd1 = smf[SMF_BDEC + c0 + 1];
                    *(uint32_t*)(g_cv + (size_t)(r0 + rowA) * CTXP + c0) =
                        bf2_bits(acc[j][0] + bd0, acc[j][1] + bd1);
                    *(uint32_t*)(g_cv + (size_t)(r0 + rowA + 8) * CTXP + c0) =
                        bf2_bits(acc[j][2] + bd0, acc[j][3] + bd1);
                }
            }
        }
    }

    lg00 += __shfl_xor_sync(0xffffffffu, lg00, 1);
    lg00 += __shfl_xor_sync(0xffffffffu, lg00, 2);
    lg01 += __shfl_xor_sync(0xffffffffu, lg01, 1);
    lg01 += __shfl_xor_sync(0xffffffffu, lg01, 2);
    lg10 += __shfl_xor_sync(0xffffffffu, lg10, 1);
    lg10 += __shfl_xor_sync(0xffffffffu, lg10, 2);
    lg11 += __shfl_xor_sync(0xffffffffu, lg11, 1);
    lg11 += __shfl_xor_sync(0xffffffffu, lg11, 2);
    if ((lane & 3) == 0) {
        const int base = nhalf ? SMF_LGQ : SMF_LGP;
        smf[base + rowA * 2]           = lg00;
        smf[base + rowA * 2 + 1]       = lg01;
        smf[base + (rowA + 8) * 2]     = lg10;
        smf[base + (rowA + 8) * 2 + 1] = lg11;
    }
    __syncthreads();
    if (tid < ROWS) {
        const float l0 = smf[SMF_LGP + tid * 2]     + smf[SMF_LGQ + tid * 2]     + b_cls[0];
        const float l1 = smf[SMF_LGP + tid * 2 + 1] + smf[SMF_LGQ + tid * 2 + 1] + b_cls[1];
        const float m  = fmaxf(l0, l1);
        const float lse = m + log1pf(__expf(fminf(l0, l1) - m));
        smf[SMF_NLL + tid] = lse - (labels[r0 + tid] ? l1 : l0);
    }
    __syncthreads();
    if (tid == 0) {
        float sn = 0.f;
        #pragma unroll
        for (int i = 0; i < ROWS; ++i) sn += smf[SMF_NLL + i];
        g_nll[gb] = sn;
    }
}

// ---------------------------------------------------------------------------
// Dot kernel: proven R12 config — 1024 blocks x 128 threads, 48 regs,
// bf16x2-FMA accumulation, cv cached in registers across the 3 rounds.
// ---------------------------------------------------------------------------
__global__ __launch_bounds__(128) void dot_kernel(const int* __restrict__ ctx_ids,
                                                  const int* __restrict__ neg_ids)
{
    __shared__ float sden[16];
    const int tid  = threadIdx.x;
    const int wid  = tid >> 5;
    const int lane = tid & 31;
    const int o    = lane >> 3;
    const int l    = lane & 7;
    const int r0   = blockIdx.x * 32;

    float accDeno = 0.f;

    #pragma unroll 1
    for (int t = 0; t < 8; ++t) {
        const int gr = r0 + wid * 8 + t;
        const uint4* cv = (const uint4*)(g_cv + (size_t)gr * CTXP);

        uint4 cvr[5];
        #pragma unroll
        for (int s = 0; s < 5; ++s) {
            const int e = s * 8 + l;
            cvr[s] = (e < 38) ? cv[e] : make_uint4(0u, 0u, 0u, 0u);
        }

        #pragma unroll
        for (int round = 0; round < 3; ++round) {
            const int j = round * 4 + o;
            const bool valid = (j < 11);
            int widx = 0;
            if (valid) widx = (j == 0) ? ctx_ids[gr] : neg_ids[gr * KNEG + (j - 1)];
            const uint4* xp = (const uint4*)(g_ctx + (size_t)widx * CTXP);

            uint32_t a0 = 0u, a1 = 0u;
            #pragma unroll
            for (int s = 0; s < 5; ++s) {
                const int e = s * 8 + l;
                if (e < 38) {
                    const uint4 x = xp[e];
                    BFMA2(a0, cvr[s].x, x.x);
                    BFMA2(a1, cvr[s].y, x.y);
                    BFMA2(a0, cvr[s].z, x.z);
                    BFMA2(a1, cvr[s].w, x.w);
                }
            }
            const float2 f0 = __bfloat1622float2(*(const __nv_bfloat162*)&a0);
            const float2 f1 = __bfloat1622float2(*(const __nv_bfloat162*)&a1);
            float acc = (f0.x + f0.y) + (f1.x + f1.y);

            acc += __shfl_down_sync(0xffffffffu, acc, 4, 8);
            acc += __shfl_down_sync(0xffffffffu, acc, 2, 8);
            acc += __shfl_down_sync(0xffffffffu, acc, 1, 8);

            if (l == 0 && valid) {
                const float s1 = fminf(fmaxf(acc, -10.f), 10.f);
                accDeno += (j == 0) ? log1pf(__expf(-s1)) : log1pf(__expf(s1));
            }
        }
    }
    if (l == 0) sden[wid * 4 + o] = accDeno;
    __syncthreads();
    if (tid == 0) {
        float sd = 0.f;
        #pragma unroll
        for (int i = 0; i < 16; ++i) sd += sden[i];
        g_deno[blockIdx.x] = sd;
    }
}

__global__ __launch_bounds__(256) void finalize_kernel(float* __restrict__ out)
{
    __shared__ float sd[256], sn[256];
    const int t = threadIdx.x;
    sd[t] = g_deno[t] + g_deno[t + 256] + g_deno[t + 512] + g_deno[t + 768];
    sn[t] = g_nll[t]  + g_nll[t + 256];
    __syncthreads();
    for (int ofs = 128; ofs > 0; ofs >>= 1) {
        if (t < ofs) { sd[t] += sd[t + ofs]; sn[t] += sn[t + ofs]; }
        __syncthreads();
    }
    if (t == 0) {
        const float invB = 1.0f / (float)BATCH;
        float deno = fminf(fmaxf(sd[0] * invB, 1e-5f), 10.f);
        float cono = fminf(fmaxf(sn[0] * invB, 1e-5f), 10.f);
        out[0] = fmaxf(deno + cono, 1e-5f);
        out[1] = deno;
        out[2] = cono;
    }
}

extern "C" void kernel_launch(void* const* d_in, const int* in_sizes, int n_in,
                              void* d_out, int out_size)
{
    const int*   cen_ids = (const int*)  d_in[0];
    const int*   ctx_ids = (const int*)  d_in[1];
    const int*   neg_ids = (const int*)  d_in[2];
    const int*   labels  = (const int*)  d_in[3];
    const float* cen_emb = (const float*)d_in[4];
    const float* ctx_emb = (const float*)d_in[5];
    const float* W_enc   = (const float*)d_in[6];
    const float* b_enc   = (const float*)d_in[7];
    const float* W_dec   = (const float*)d_in[8];
    const float* b_dec   = (const float*)d_in[9];
    const float* W_cls   = (const float*)d_in[10];
    const float* b_cls   = (const float*)d_in[11];

    const int cBlocks = (2 * KPAD * KPAD + 255) / 256;
    convert_w2<<<cBlocks, 256>>>(W_enc, W_dec);

    cudaFuncSetAttribute(hetero_kernel,
                         cudaFuncAttributeMaxDynamicSharedMemorySize, SM_TOTAL);
    hetero_kernel<<<GRID, THREADS, SM_TOTAL>>>(
        cen_ids, labels, cen_emb, ctx_emb, b_enc, b_dec, W_cls, b_cls);
    dot_kernel<<<DOTBLK, 128>>>(ctx_ids, neg_ids);
    finalize_kernel<<<1, 256>>>((float*)d_out);
}